// round 10
// baseline (speedup 1.0000x reference)
#include <cuda_runtime.h>
#include <mma.h>
#include <math.h>

using namespace nvcuda;

#define BSZ   256
#define ISIZE 256
#define HSIZE 512
#define BH    (BSZ*HSIZE)

#define NGATE  128            // 4 gates x 32 tiles (64x64), full K per unit
#define NSLOTS (NGATE + 512)  // + 512 reduce units (b, row-half)
#define GRID1  296            // 2 CTAs/SM x 148 SMs

// Scratch (device globals)
__device__ __align__(16) float g_pre[4*BH];     // gate preactivations (full)
__device__ __align__(16) float g_hredp[8*BH];   // hred partials (2 halves x 4 groups)
__device__ __align__(16) float g_ei[BH];        // eta*its per (b,k)

// ---------------------------------------------------------------------------
// K1: heterogeneous persistent kernel, 296 CTAs x 512 threads.
//  slots [0,128):   tf32 tensor-core gate GEMM units (error-compensated)
//  slots [128,640): barrier-free streaming reduce units (b, row-half)
// Gate path uses the TENSOR pipe + L2-resident operands -> no FMA wall.
// ---------------------------------------------------------------------------
__global__ __launch_bounds__(512, 2)
void k1(const float* __restrict__ x, const float* __restrict__ h0,
        const float* __restrict__ hebb,
        const float* __restrict__ x2f, const float* __restrict__ x2i,
        const float* __restrict__ x2o, const float* __restrict__ x2c,
        const float* __restrict__ h2f, const float* __restrict__ h2i,
        const float* __restrict__ h2o, const float* __restrict__ w)
{
    int tid = threadIdx.x;

    for (int s = blockIdx.x; s < NSLOTS; s += GRID1) {
        if (s >= NGATE) {
            // ---- reduce unit (b, half): barrier-free, 8 global partials ---
            int ru = s - NGATE;
            int b = ru >> 1;
            int half = ru & 1;
            int g = tid >> 7;              // row-group 0..3 (64 rows)
            int c = tid & 127;             // f4 column
            int hbase = half * 256 + g * 64;
            const float4* hb4 = (const float4*)(hebb + (size_t)b * HSIZE * HSIZE)
                                + (size_t)hbase * 128 + c;
            const float* h0p = h0 + b * HSIZE + hbase;
            float4 acc = make_float4(0.f, 0.f, 0.f, 0.f);
#pragma unroll 8
            for (int i = 0; i < 64; ++i) {
                float sv = __ldg(h0p + i);
                float4 v = hb4[(size_t)i * 128];
                acc.x = fmaf(sv, v.x, acc.x);
                acc.y = fmaf(sv, v.y, acc.y);
                acc.z = fmaf(sv, v.z, acc.z);
                acc.w = fmaf(sv, v.w, acc.w);
            }
            int p = half * 4 + g;
            ((float4*)(g_hredp + (size_t)p * BH + b * HSIZE))[c] = acc;
        } else {
            // ---- tf32 tensor gate unit: 64x64 tile, full K (768) ----------
            int gate = s >> 5;
            int ct = s & 31;
            int bn0 = (ct & 7) * 64;       // k (output col) offset
            int bm0 = (ct >> 3) * 64;      // b (output row) offset
            const float* xw = (gate == 0) ? x2f : (gate == 1) ? x2i
                            : (gate == 2) ? x2o : x2c;
            const float* hw = (gate == 0) ? h2f : (gate == 1) ? h2i
                            : (gate == 2) ? h2o : w;
            bool trans = (gate == 3);      // w stored [j,k]; others [k,j]

            int wid = tid >> 5;
            int wy = wid >> 2;             // 0..3: 16-row block
            int wx = wid & 3;              // 0..3: 16-col block
            int am0 = bm0 + wy * 16;
            int an0 = bn0 + wx * 16;

            wmma::fragment<wmma::accumulator, 16, 16, 8, float> accf;
            wmma::fill_fragment(accf, 0.0f);

            wmma::fragment<wmma::matrix_a, 16, 16, 8, wmma::precision::tf32,
                           wmma::row_major> af, ahi, alo;
            wmma::fragment<wmma::matrix_b, 16, 16, 8, wmma::precision::tf32,
                           wmma::col_major> bc, bchi, bclo;
            wmma::fragment<wmma::matrix_b, 16, 16, 8, wmma::precision::tf32,
                           wmma::row_major> br, brhi, brlo;

            for (int kc = 0; kc < 96; ++kc) {
                const float* A;
                int KA, j0;
                if (kc < 32) { A = x;  KA = ISIZE; j0 = kc * 8; }
                else         { A = h0; KA = HSIZE; j0 = (kc - 32) * 8; }

                wmma::load_matrix_sync(af, A + (size_t)am0 * KA + j0, KA);
#pragma unroll
                for (int i = 0; i < af.num_elements; i++) {
                    float v = af.x[i];
                    float hi = wmma::__float_to_tf32(v);
                    ahi.x[i] = hi;
                    alo.x[i] = wmma::__float_to_tf32(v - hi);
                }

                bool useTrans = (kc >= 32) && trans;
                if (!useTrans) {
                    const float* W = (kc < 32) ? xw : hw;
                    int WK = (kc < 32) ? ISIZE : HSIZE;
                    wmma::load_matrix_sync(bc, W + (size_t)an0 * WK + j0, WK);
#pragma unroll
                    for (int i = 0; i < bc.num_elements; i++) {
                        float v = bc.x[i];
                        float hi = wmma::__float_to_tf32(v);
                        bchi.x[i] = hi;
                        bclo.x[i] = wmma::__float_to_tf32(v - hi);
                    }
                    wmma::mma_sync(accf, ahi, bchi, accf);
                    wmma::mma_sync(accf, ahi, bclo, accf);
                    wmma::mma_sync(accf, alo, bchi, accf);
                } else {
                    wmma::load_matrix_sync(br, w + (size_t)j0 * HSIZE + an0, HSIZE);
#pragma unroll
                    for (int i = 0; i < br.num_elements; i++) {
                        float v = br.x[i];
                        float hi = wmma::__float_to_tf32(v);
                        brhi.x[i] = hi;
                        brlo.x[i] = wmma::__float_to_tf32(v - hi);
                    }
                    wmma::mma_sync(accf, ahi, brhi, accf);
                    wmma::mma_sync(accf, ahi, brlo, accf);
                    wmma::mma_sync(accf, alo, brhi, accf);
                }
            }
            float* outb = g_pre + (size_t)gate * BH;
            wmma::store_matrix_sync(outb + (size_t)am0 * HSIZE + an0, accf,
                                    HSIZE, wmma::mem_row_major);
        }
    }
}

// ---------------------------------------------------------------------------
// K2: per-batch cell/hactiv + modulation scalar + ei = (m*mfw+mfb)*its.
// ---------------------------------------------------------------------------
__global__ __launch_bounds__(HSIZE)
void k2(const float* __restrict__ c0, const float* __restrict__ alpha,
        const float* __restrict__ x2f_b, const float* __restrict__ h2f_b,
        const float* __restrict__ x2i_b, const float* __restrict__ h2i_b,
        const float* __restrict__ x2o_b, const float* __restrict__ h2o_b,
        const float* __restrict__ x2c_b,
        const float* __restrict__ h2mod_w, const float* __restrict__ h2mod_b,
        const float* __restrict__ mfw, const float* __restrict__ mfb,
        float* __restrict__ out_hact, float* __restrict__ out_cell)
{
    __shared__ float sred[16];
    __shared__ float smv;
    int b = blockIdx.x;
    int k = threadIdx.x;
    int idx = b * HSIZE + k;

    float hred = 0.f;
#pragma unroll
    for (int p = 0; p < 8; p++) hred += g_hredp[(size_t)p * BH + idx];

    float pf = g_pre[idx]          + x2f_b[k] + h2f_b[k];
    float pi = g_pre[BH + idx]     + x2i_b[k] + h2i_b[k];
    float po = g_pre[2 * BH + idx] + x2o_b[k] + h2o_b[k];
    float pc = g_pre[3 * BH + idx] + x2c_b[k] + alpha[k] * hred;
    float fgt = 1.f / (1.f + expf(-pf));
    float ipt = 1.f / (1.f + expf(-pi));
    float opt = 1.f / (1.f + expf(-po));
    float its = tanhf(pc);
    float cell = fgt * c0[idx] + ipt * its;
    float hact = opt * tanhf(cell);
    out_cell[idx] = cell;
    out_hact[idx] = hact;

    float mv = hact * h2mod_w[k];
#pragma unroll
    for (int o = 16; o > 0; o >>= 1) mv += __shfl_down_sync(0xffffffffu, mv, o);
    if ((k & 31) == 0) sred[k >> 5] = mv;
    __syncthreads();
    if (k == 0) {
        float s = 0.f;
#pragma unroll
        for (int i = 0; i < 16; i++) s += sred[i];
        smv = tanhf(s + h2mod_b[0]);
    }
    __syncthreads();
    g_ei[idx] = fmaf(smv, mfw[k], mfb[k]) * its;
}

// ---------------------------------------------------------------------------
// K3: hebb_new[b,h,k] = clip(hebb + h0[b,h]*ei[b,k], -2, 2). Pure streaming.
// ---------------------------------------------------------------------------
__global__ __launch_bounds__(256)
void k3(const float4* __restrict__ hebb4, const float* __restrict__ h0,
        float4* __restrict__ out4)
{
    const float4* ei4 = reinterpret_cast<const float4*>(g_ei);
    int base = blockIdx.x * 1024 + threadIdx.x;
#pragma unroll
    for (int j = 0; j < 4; j++) {
        int idx = base + j * 256;
        int k4 = idx & 127;
        int bh = idx >> 7;
        int b = bh >> 9;
        float s = h0[bh];
        float4 e = ei4[(b << 7) + k4];
        float4 hv = hebb4[idx];
        float v;
        v = fmaf(s, e.x, hv.x); hv.x = fminf(fmaxf(v, -2.f), 2.f);
        v = fmaf(s, e.y, hv.y); hv.y = fminf(fmaxf(v, -2.f), 2.f);
        v = fmaf(s, e.z, hv.z); hv.z = fminf(fmaxf(v, -2.f), 2.f);
        v = fmaf(s, e.w, hv.w); hv.w = fminf(fmaxf(v, -2.f), 2.f);
        out4[idx] = hv;
    }
}

// ---------------------------------------------------------------------------
extern "C" void kernel_launch(void* const* d_in, const int* in_sizes, int n_in,
                              void* d_out, int out_size)
{
    const float* inputs  = (const float*)d_in[0];
    const float* h0      = (const float*)d_in[1];
    const float* c0      = (const float*)d_in[2];
    const float* hebb    = (const float*)d_in[3];
    const float* w       = (const float*)d_in[4];
    const float* alpha   = (const float*)d_in[5];
    const float* h2f_w   = (const float*)d_in[6];
    const float* h2f_b   = (const float*)d_in[7];
    const float* h2i_w   = (const float*)d_in[8];
    const float* h2i_b   = (const float*)d_in[9];
    const float* h2o_w   = (const float*)d_in[10];
    const float* h2o_b   = (const float*)d_in[11];
    const float* x2f_w   = (const float*)d_in[12];
    const float* x2f_b   = (const float*)d_in[13];
    const float* x2i_w   = (const float*)d_in[14];
    const float* x2i_b   = (const float*)d_in[15];
    const float* x2o_w   = (const float*)d_in[16];
    const float* x2o_b   = (const float*)d_in[17];
    const float* x2c_w   = (const float*)d_in[18];
    const float* x2c_b   = (const float*)d_in[19];
    const float* h2mod_w = (const float*)d_in[20];
    const float* h2mod_b = (const float*)d_in[21];
    const float* mfw     = (const float*)d_in[22];
    const float* mfb     = (const float*)d_in[23];

    float* out       = (float*)d_out;
    float* out_hact  = out;              // [B,H]
    float* out_cell  = out + BH;         // [B,H]
    float* out_hebb  = out + 2 * BH;     // [B,H,H]

    // K1: tensor-core gates + streaming reduce
    k1<<<GRID1, 512>>>(inputs, h0, hebb,
                       x2f_w, x2i_w, x2o_w, x2c_w,
                       h2f_w, h2i_w, h2o_w, w);

    // K2: cell / hactiv / m / ei
    k2<<<BSZ, HSIZE>>>(c0, alpha, x2f_b, h2f_b, x2i_b, h2i_b, x2o_b, h2o_b,
                       x2c_b, h2mod_w, h2mod_b, mfw, mfb, out_hact, out_cell);

    // K3: hebb update (268MB R + 268MB W streaming)
    int nblk = (BSZ * HSIZE * HSIZE / 4) / 1024;   // 8192
    k3<<<nblk, 256>>>((const float4*)hebb, h0, (float4*)out_hebb);
}